// round 15
// baseline (speedup 1.0000x reference)
#include <cuda_runtime.h>
#include <cuda_fp16.h>
#include <cuda_bf16.h>

#define NV 100000
#define TT 128
#define NE 1600000
#define KK 9
#define NCHUNK 98           // ceil(NV/1024)
#define CNT_BLK 6250        // NE/256
#define CONV_BLK 12500      // NV/8
#define ZERO_BLK 391        // ceil(NV/256)

// Scratch (no allocations allowed -> __device__ globals, zero-initialized).
__device__ __half g_hA [(size_t)NV * TT];   // fp16 ping (25.6MB)
__device__ __half g_hB [(size_t)NV * TT];   // fp16 pong (25.6MB)
__device__ float  g_inv[NV];
__device__ int    g_deg[NV];                // zero at load; re-zeroed each call
__device__ int    g_start[NV + 1];
__device__ int    g_pos[NE];                // per-edge rank within its dst node
__device__ int    g_csr[NE];

// ---------------------------------------------------------------------------
// fp16 row helpers: lane l holds t = 4l..4l+3 (8 bytes per lane).
__device__ __forceinline__ void acc_u2(float4& acc, uint2 u) {
    float2 a = __half22float2(*reinterpret_cast<__half2*>(&u.x));
    float2 b = __half22float2(*reinterpret_cast<__half2*>(&u.y));
    acc.x += a.x; acc.y += a.y; acc.z += b.x; acc.w += b.y;
}

__device__ __forceinline__ void store_row(__half* __restrict__ h, int n, int lane,
                                          float4 v) {
    uint2 u;
    *reinterpret_cast<__half2*>(&u.x) = __floats2half2_rn(v.x, v.y);
    *reinterpret_cast<__half2*>(&u.y) = __floats2half2_rn(v.z, v.w);
    *(uint2*)(h + (size_t)n * TT + lane * 4) = u;
}

// Register conv1d (K=9) across a warp-held row (fp32).
__device__ __forceinline__ float4 conv_shfl(float4 v, const float* __restrict__ wt,
                                            float bias, int lane) {
    float c[12];
    c[4] = v.x; c[5] = v.y; c[6] = v.z; c[7] = v.w;
    c[0] = __shfl_up_sync(~0u, v.x, 1);
    c[1] = __shfl_up_sync(~0u, v.y, 1);
    c[2] = __shfl_up_sync(~0u, v.z, 1);
    c[3] = __shfl_up_sync(~0u, v.w, 1);
    c[8]  = __shfl_down_sync(~0u, v.x, 1);
    c[9]  = __shfl_down_sync(~0u, v.y, 1);
    c[10] = __shfl_down_sync(~0u, v.z, 1);
    c[11] = __shfl_down_sync(~0u, v.w, 1);
    if (lane == 0)  { c[0] = c[1] = c[2] = c[3] = 0.f; }
    if (lane == 31) { c[8] = c[9] = c[10] = c[11] = 0.f; }
    float4 r;
    r.x = bias; r.y = bias; r.z = bias; r.w = bias;
#pragma unroll
    for (int k = 0; k < KK; k++) {
        r.x += wt[k] * c[k];
        r.y += wt[k] * c[k + 1];
        r.z += wt[k] * c[k + 2];
        r.w += wt[k] * c[k + 3];
    }
    return r;
}

// ---------------------------------------------------------------------------
// Fused: degree count + per-edge rank capture (blocks 0..CNT_BLK-1) +
// layer-0 conv (remaining blocks). Independent work sharing one launch.
__global__ void count_conv0_kernel(const int* __restrict__ ei,
                                   const float* __restrict__ bout,
                                   float* __restrict__ out,
                                   const float* __restrict__ xin,
                                   const float* __restrict__ cw,
                                   const float* __restrict__ cb,
                                   __half* __restrict__ h) {
    int b = blockIdx.x;
    if (b < CNT_BLK) {
        int e = b * 256 + threadIdx.x;
        if (e < NE) g_pos[e] = atomicAdd(&g_deg[__ldg(ei + NE + e)], 1);
        if (e < TT * 3) out[e] = bout[e % 3];
        if (e == TT * 3) g_start[NV] = NE;
    } else {
        int n = (b - CNT_BLK) * 8 + (threadIdx.x >> 5);
        int lane = threadIdx.x & 31;
        if (n >= NV) return;
        float wt[KK];
#pragma unroll
        for (int k = 0; k < KK; k++) wt[k] = cw[k];
        float4 v = *(const float4*)(xin + (size_t)n * TT + lane * 4);
        float4 r = conv_shfl(v, wt, cb[0], lane);
        store_row(h, n, lane, r);
    }
}

// Single-kernel scan: each block directly reduces deg[0..bid*1024) for its
// prefix offset (coalesced, ~20MB total extra L2), then scans its own chunk.
__global__ void scan_kernel() {
    int t = threadIdx.x;
    int l = t & 31, w = t >> 5;
    __shared__ int ws[32];
    __shared__ int s_off;

    {   // Block offset = sum of deg[j] for j < blockIdx.x * 1024.
        int lim = blockIdx.x * 1024;
        int v = 0;
        for (int i = t; i < lim; i += 1024) v += g_deg[i];
#pragma unroll
        for (int off = 16; off; off >>= 1) v += __shfl_down_sync(~0u, v, off);
        if (l == 0) ws[w] = v;
        __syncthreads();
        if (t < 32) {
            int v2 = ws[t];
#pragma unroll
            for (int off = 16; off; off >>= 1) v2 += __shfl_down_sync(~0u, v2, off);
            if (t == 0) s_off = v2;
        }
        __syncthreads();
    }

    int i = blockIdx.x * 1024 + t;
    int d = (i < NV) ? g_deg[i] : 0;
    int s = d;
#pragma unroll
    for (int off = 1; off < 32; off <<= 1) {
        int u = __shfl_up_sync(~0u, s, off);
        if (l >= off) s += u;
    }
    __syncthreads();                 // ws reuse barrier
    if (l == 31) ws[w] = s;
    __syncthreads();
    if (t < 32) {
        int v = ws[t];
#pragma unroll
        for (int off = 1; off < 32; off <<= 1) {
            int u = __shfl_up_sync(~0u, v, off);
            if (t >= off) v += u;
        }
        ws[t] = v;
    }
    __syncthreads();
    int incl = s + (w ? ws[w - 1] : 0) + s_off;
    if (i < NV) {
        g_start[i] = incl - d;
        g_inv[i]   = 1.0f / (float)(d + 1);
    }
}

// CSR fill, ATOMIC-FREE: slot = start[dst] + precomputed rank. Tail blocks
// re-zero g_deg for the next graph replay (its last reader, scan, is done).
__global__ void fill_kernel(const int* __restrict__ ei) {
    int b = blockIdx.x;
    if (b < CNT_BLK) {
        int e = b * 256 + threadIdx.x;
        if (e < NE) {
            int s = __ldg(ei + e);
            int d = __ldg(ei + NE + e);
            g_csr[g_start[d] + g_pos[e]] = s;
        }
    } else {
        int i = (b - CNT_BLK) * 256 + threadIdx.x;
        if (i < NV) g_deg[i] = 0;
    }
}

// ---------------------------------------------------------------------------
// Gather-aggregate one node's neighborhood (self + CSR), fp16 in, fp32 acc.
// Issue-bound optimization: 4 edges combined with a fp16 __hadd2 tree
// (6 HADD2) then ONE convert + fp32 accumulate (4 cvt + 4 FADD) instead of
// per-edge conversion (16 cvt + 16 FADD). Neighbor indices read as aligned
// int4 (uniform LDG.128 broadcast).
__device__ __forceinline__ float4 aggregate(const __half* __restrict__ hin,
                                            int n, int lane) {
    int beg = g_start[n], end = g_start[n + 1];
    size_t lo = (size_t)lane * 4;
    float4 acc = make_float4(0.f, 0.f, 0.f, 0.f);
    acc_u2(acc, *(const uint2*)(hin + (size_t)n * TT + lo));   // self loop

    int k = beg;
    int kal = (beg + 3) & ~3;          // first int4-aligned index
    int head_end = kal < end ? kal : end;
    for (; k < head_end; k++)
        acc_u2(acc, *(const uint2*)(hin + (size_t)g_csr[k] * TT + lo));

    for (; k + 4 <= end; k += 4) {
        int4 s4 = *(const int4*)(g_csr + k);        // aligned uniform load
        uint2 u0 = *(const uint2*)(hin + (size_t)s4.x * TT + lo);
        uint2 u1 = *(const uint2*)(hin + (size_t)s4.y * TT + lo);
        uint2 u2 = *(const uint2*)(hin + (size_t)s4.z * TT + lo);
        uint2 u3 = *(const uint2*)(hin + (size_t)s4.w * TT + lo);
        // fp16 pairwise tree over the 4 edges (values O(10), far from fp16 max)
        __half2 ax = __hadd2(__hadd2(*reinterpret_cast<__half2*>(&u0.x),
                                     *reinterpret_cast<__half2*>(&u1.x)),
                             __hadd2(*reinterpret_cast<__half2*>(&u2.x),
                                     *reinterpret_cast<__half2*>(&u3.x)));
        __half2 ay = __hadd2(__hadd2(*reinterpret_cast<__half2*>(&u0.y),
                                     *reinterpret_cast<__half2*>(&u1.y)),
                             __hadd2(*reinterpret_cast<__half2*>(&u2.y),
                                     *reinterpret_cast<__half2*>(&u3.y)));
        float2 fa = __half22float2(ax);
        float2 fb = __half22float2(ay);
        acc.x += fa.x; acc.y += fa.y; acc.z += fb.x; acc.w += fb.y;
    }
    for (; k < end; k++)
        acc_u2(acc, *(const uint2*)(hin + (size_t)g_csr[k] * TT + lo));
    return acc;
}

// Fused agg + mean + relu + next conv (layers 1, 2).
__global__ void agg_conv_kernel(const __half* __restrict__ hin,
                                __half* __restrict__ hout,
                                const float* __restrict__ cw,
                                const float* __restrict__ cb,
                                int layer) {
    int n = blockIdx.x * 8 + (threadIdx.x >> 5);
    int lane = threadIdx.x & 31;
    if (n >= NV) return;
    float4 acc = aggregate(hin, n, lane);
    float inv = g_inv[n];
    float4 v;
    v.x = fmaxf(acc.x * inv, 0.f);
    v.y = fmaxf(acc.y * inv, 0.f);
    v.z = fmaxf(acc.z * inv, 0.f);
    v.w = fmaxf(acc.w * inv, 0.f);
    float wt[KK];
#pragma unroll
    for (int q = 0; q < KK; q++) wt[q] = cw[layer * KK + q];
    v = conv_shfl(v, wt, cb[layer], lane);
    store_row(hout, n, lane, v);
}

// Fused final agg + mean + relu + output matvec with flat-reshape semantics:
// value of node n at time t sits at flat f = n*128+t of x.reshape(128, NV);
// contributes to out[i = f/NV, c] with weight W[c*NV + (f%NV)].
// Fast path: whole node-row inside one output row (all but 127 nodes).
__global__ void agg_out_kernel(const __half* __restrict__ hin,
                               const float* __restrict__ W,
                               float* __restrict__ out) {
    __shared__ float sm[8][TT * 3];   // per-warp accumulator banks
    int w = threadIdx.x >> 5, lane = threadIdx.x & 31;
    for (int i = threadIdx.x; i < 8 * TT * 3; i += 256)
        ((float*)sm)[i] = 0.f;
    __syncthreads();

    int stride = gridDim.x * 8;
    for (int n = blockIdx.x * 8 + w; n < NV; n += stride) {
        float4 acc = aggregate(hin, n, lane);
        float inv = g_inv[n];
        float v[4];
        v[0] = fmaxf(acc.x * inv, 0.f);
        v[1] = fmaxf(acc.y * inv, 0.f);
        v[2] = fmaxf(acc.z * inv, 0.f);
        v[3] = fmaxf(acc.w * inv, 0.f);

        int fbase = n * TT;              // flat index of t=0
        int i0 = fbase / NV;
        int j0 = fbase - i0 * NV;        // column of t=0 (multiple of 4)

        if (j0 + TT <= NV) {
            // Fast path: single output row; coalesced float4 W loads.
            int j = j0 + lane * 4;
            float4 w0 = *(const float4*)(W + j);
            float4 w1 = *(const float4*)(W + NV + j);
            float4 w2 = *(const float4*)(W + 2 * NV + j);
            float s0 = v[0] * w0.x + v[1] * w0.y + v[2] * w0.z + v[3] * w0.w;
            float s1 = v[0] * w1.x + v[1] * w1.y + v[2] * w1.z + v[3] * w1.w;
            float s2 = v[0] * w2.x + v[1] * w2.y + v[2] * w2.z + v[3] * w2.w;
#pragma unroll
            for (int off = 16; off; off >>= 1) {
                s0 += __shfl_down_sync(~0u, s0, off);
                s1 += __shfl_down_sync(~0u, s1, off);
                s2 += __shfl_down_sync(~0u, s2, off);
            }
            if (lane == 0) {
                sm[w][i0 * 3 + 0] += s0;
                sm[w][i0 * 3 + 1] += s1;
                sm[w][i0 * 3 + 2] += s2;
            }
        } else {
            // Slow path: node-row straddles an output-row boundary.
            int B = (i0 + 1) * NV;
            int f = fbase + lane * 4;
            float s0[3] = {0.f, 0.f, 0.f}, s1[3] = {0.f, 0.f, 0.f};
#pragma unroll
            for (int q = 0; q < 4; q++) {
                int fq = f + q;
                bool hi = fq >= B;
                int j = fq - (hi ? B : i0 * NV);
                float w0 = __ldg(W + j);
                float w1 = __ldg(W + NV + j);
                float w2 = __ldg(W + 2 * NV + j);
                if (hi) { s1[0] += v[q] * w0; s1[1] += v[q] * w1; s1[2] += v[q] * w2; }
                else    { s0[0] += v[q] * w0; s0[1] += v[q] * w1; s0[2] += v[q] * w2; }
            }
#pragma unroll
            for (int off = 16; off; off >>= 1) {
                s0[0] += __shfl_down_sync(~0u, s0[0], off);
                s0[1] += __shfl_down_sync(~0u, s0[1], off);
                s0[2] += __shfl_down_sync(~0u, s0[2], off);
                s1[0] += __shfl_down_sync(~0u, s1[0], off);
                s1[1] += __shfl_down_sync(~0u, s1[1], off);
                s1[2] += __shfl_down_sync(~0u, s1[2], off);
            }
            if (lane == 0) {
                sm[w][i0 * 3 + 0] += s0[0];
                sm[w][i0 * 3 + 1] += s0[1];
                sm[w][i0 * 3 + 2] += s0[2];
                sm[w][(i0 + 1) * 3 + 0] += s1[0];
                sm[w][(i0 + 1) * 3 + 1] += s1[1];
                sm[w][(i0 + 1) * 3 + 2] += s1[2];
            }
        }
    }
    __syncthreads();
    for (int i = threadIdx.x; i < TT * 3; i += 256) {
        float s = 0.f;
#pragma unroll
        for (int ww = 0; ww < 8; ww++) s += sm[ww][i];
        atomicAdd(&out[i], s);
    }
}

// ---------------------------------------------------------------------------
extern "C" void kernel_launch(void* const* d_in, const int* in_sizes, int n_in,
                              void* d_out, int out_size) {
    const float* x  = (const float*)d_in[0];
    const int*   ei = (const int*)  d_in[1];
    const float* cw = (const float*)d_in[2];
    const float* cb = (const float*)d_in[3];
    const float* W  = (const float*)d_in[4];
    const float* bo = (const float*)d_in[5];
    float* out = (float*)d_out;

    __half *hA, *hB;
    cudaGetSymbolAddress((void**)&hA, g_hA);
    cudaGetSymbolAddress((void**)&hB, g_hB);

    // CSR build; g_deg is zero (load-time init on call 1, re-zeroed by
    // fill_kernel's tail blocks on every call for graph replays).
    count_conv0_kernel<<<CNT_BLK + CONV_BLK, 256>>>(ei, bo, out, x, cw, cb, hA);
    scan_kernel<<<NCHUNK, 1024>>>();
    fill_kernel<<<CNT_BLK + ZERO_BLK, 256>>>(ei);

    int gagg = (NV + 7) / 8;
    agg_conv_kernel<<<gagg, 256>>>(hA, hB, cw, cb, 1);
    agg_conv_kernel<<<gagg, 256>>>(hB, hA, cw, cb, 2);
    agg_out_kernel<<<1184, 256>>>(hA, W, out);
}

// round 16
// speedup vs baseline: 1.0561x; 1.0561x over previous
#include <cuda_runtime.h>
#include <cuda_fp16.h>
#include <cuda_bf16.h>

#define NV 100000
#define TT 128
#define NE 1600000
#define KK 9
#define NCHUNK 98           // ceil(NV/1024)
#define CNT_BLK 6250        // NE/256
#define CONV_BLK 12500      // NV/8
#define ZERO_BLK 391        // ceil(NV/256)

// Scratch (no allocations allowed -> __device__ globals, zero-initialized).
__device__ __half g_hA [(size_t)NV * TT];   // fp16 ping (25.6MB)
__device__ __half g_hB [(size_t)NV * TT];   // fp16 pong (25.6MB)
__device__ float  g_inv[NV];
__device__ int    g_deg[NV];                // zero at load; re-zeroed each call
__device__ int    g_start[NV + 1];
__device__ int    g_pos[NE];                // per-edge rank within its dst node
__device__ int    g_csr[NE];

// ---------------------------------------------------------------------------
// fp16 row helpers: lane l holds t = 4l..4l+3 (8 bytes per lane).
__device__ __forceinline__ void acc_u2(float4& acc, uint2 u) {
    float2 a = __half22float2(*reinterpret_cast<__half2*>(&u.x));
    float2 b = __half22float2(*reinterpret_cast<__half2*>(&u.y));
    acc.x += a.x; acc.y += a.y; acc.z += b.x; acc.w += b.y;
}

__device__ __forceinline__ void store_row(__half* __restrict__ h, int n, int lane,
                                          float4 v) {
    uint2 u;
    *reinterpret_cast<__half2*>(&u.x) = __floats2half2_rn(v.x, v.y);
    *reinterpret_cast<__half2*>(&u.y) = __floats2half2_rn(v.z, v.w);
    *(uint2*)(h + (size_t)n * TT + lane * 4) = u;
}

// Register conv1d (K=9) across a warp-held row (fp32).
__device__ __forceinline__ float4 conv_shfl(float4 v, const float* __restrict__ wt,
                                            float bias, int lane) {
    float c[12];
    c[4] = v.x; c[5] = v.y; c[6] = v.z; c[7] = v.w;
    c[0] = __shfl_up_sync(~0u, v.x, 1);
    c[1] = __shfl_up_sync(~0u, v.y, 1);
    c[2] = __shfl_up_sync(~0u, v.z, 1);
    c[3] = __shfl_up_sync(~0u, v.w, 1);
    c[8]  = __shfl_down_sync(~0u, v.x, 1);
    c[9]  = __shfl_down_sync(~0u, v.y, 1);
    c[10] = __shfl_down_sync(~0u, v.z, 1);
    c[11] = __shfl_down_sync(~0u, v.w, 1);
    if (lane == 0)  { c[0] = c[1] = c[2] = c[3] = 0.f; }
    if (lane == 31) { c[8] = c[9] = c[10] = c[11] = 0.f; }
    float4 r;
    r.x = bias; r.y = bias; r.z = bias; r.w = bias;
#pragma unroll
    for (int k = 0; k < KK; k++) {
        r.x += wt[k] * c[k];
        r.y += wt[k] * c[k + 1];
        r.z += wt[k] * c[k + 2];
        r.w += wt[k] * c[k + 3];
    }
    return r;
}

// ---------------------------------------------------------------------------
// Fused: degree count + per-edge rank capture (blocks 0..CNT_BLK-1) +
// layer-0 conv (remaining blocks). Independent work sharing one launch.
__global__ void count_conv0_kernel(const int* __restrict__ ei,
                                   const float* __restrict__ bout,
                                   float* __restrict__ out,
                                   const float* __restrict__ xin,
                                   const float* __restrict__ cw,
                                   const float* __restrict__ cb,
                                   __half* __restrict__ h) {
    int b = blockIdx.x;
    if (b < CNT_BLK) {
        int e = b * 256 + threadIdx.x;
        if (e < NE) g_pos[e] = atomicAdd(&g_deg[__ldg(ei + NE + e)], 1);
        if (e < TT * 3) out[e] = bout[e % 3];
        if (e == TT * 3) g_start[NV] = NE;
    } else {
        int n = (b - CNT_BLK) * 8 + (threadIdx.x >> 5);
        int lane = threadIdx.x & 31;
        if (n >= NV) return;
        float wt[KK];
#pragma unroll
        for (int k = 0; k < KK; k++) wt[k] = cw[k];
        float4 v = *(const float4*)(xin + (size_t)n * TT + lane * 4);
        float4 r = conv_shfl(v, wt, cb[0], lane);
        store_row(h, n, lane, r);
    }
}

// Single-kernel scan: each block directly reduces deg[0..bid*1024) for its
// prefix offset (coalesced, ~20MB total extra L2), then scans its own chunk.
__global__ void scan_kernel() {
    int t = threadIdx.x;
    int l = t & 31, w = t >> 5;
    __shared__ int ws[32];
    __shared__ int s_off;

    {   // Block offset = sum of deg[j] for j < blockIdx.x * 1024.
        int lim = blockIdx.x * 1024;
        int v = 0;
        for (int i = t; i < lim; i += 1024) v += g_deg[i];
#pragma unroll
        for (int off = 16; off; off >>= 1) v += __shfl_down_sync(~0u, v, off);
        if (l == 0) ws[w] = v;
        __syncthreads();
        if (t < 32) {
            int v2 = ws[t];
#pragma unroll
            for (int off = 16; off; off >>= 1) v2 += __shfl_down_sync(~0u, v2, off);
            if (t == 0) s_off = v2;
        }
        __syncthreads();
    }

    int i = blockIdx.x * 1024 + t;
    int d = (i < NV) ? g_deg[i] : 0;
    int s = d;
#pragma unroll
    for (int off = 1; off < 32; off <<= 1) {
        int u = __shfl_up_sync(~0u, s, off);
        if (l >= off) s += u;
    }
    __syncthreads();                 // ws reuse barrier
    if (l == 31) ws[w] = s;
    __syncthreads();
    if (t < 32) {
        int v = ws[t];
#pragma unroll
        for (int off = 1; off < 32; off <<= 1) {
            int u = __shfl_up_sync(~0u, v, off);
            if (t >= off) v += u;
        }
        ws[t] = v;
    }
    __syncthreads();
    int incl = s + (w ? ws[w - 1] : 0) + s_off;
    if (i < NV) {
        g_start[i] = incl - d;
        g_inv[i]   = 1.0f / (float)(d + 1);
    }
}

// CSR fill, ATOMIC-FREE: slot = start[dst] + precomputed rank. Tail blocks
// re-zero g_deg for the next graph replay (its last reader, scan, is done).
__global__ void fill_kernel(const int* __restrict__ ei) {
    int b = blockIdx.x;
    if (b < CNT_BLK) {
        int e = b * 256 + threadIdx.x;
        if (e < NE) {
            int s = __ldg(ei + e);
            int d = __ldg(ei + NE + e);
            g_csr[g_start[d] + g_pos[e]] = s;
        }
    } else {
        int i = (b - CNT_BLK) * 256 + threadIdx.x;
        if (i < NV) g_deg[i] = 0;
    }
}

// ---------------------------------------------------------------------------
// Gather-aggregate one node's neighborhood (self + CSR), fp16 in, fp32 acc.
// Round-13 loop structure (single k+=4 loop, scalar index loads, no
// alignment branches). Only the reduction body changed: pairwise __hadd2
// of edge pairs (4 HADD2 + 8 cvt + 8 FADD vs 16 cvt + 16 FADD).
__device__ __forceinline__ float4 aggregate(const __half* __restrict__ hin,
                                            int n, int lane) {
    int beg = g_start[n], end = g_start[n + 1];
    size_t lo = (size_t)lane * 4;
    float4 acc = make_float4(0.f, 0.f, 0.f, 0.f);
    acc_u2(acc, *(const uint2*)(hin + (size_t)n * TT + lo));   // self loop
    int k = beg;
    for (; k + 4 <= end; k += 4) {
        int s0 = g_csr[k], s1 = g_csr[k + 1], s2 = g_csr[k + 2], s3 = g_csr[k + 3];
        uint2 u0 = *(const uint2*)(hin + (size_t)s0 * TT + lo);
        uint2 u1 = *(const uint2*)(hin + (size_t)s1 * TT + lo);
        uint2 u2 = *(const uint2*)(hin + (size_t)s2 * TT + lo);
        uint2 u3 = *(const uint2*)(hin + (size_t)s3 * TT + lo);
        __half2 x01 = __hadd2(*reinterpret_cast<__half2*>(&u0.x),
                              *reinterpret_cast<__half2*>(&u1.x));
        __half2 x23 = __hadd2(*reinterpret_cast<__half2*>(&u2.x),
                              *reinterpret_cast<__half2*>(&u3.x));
        __half2 y01 = __hadd2(*reinterpret_cast<__half2*>(&u0.y),
                              *reinterpret_cast<__half2*>(&u1.y));
        __half2 y23 = __hadd2(*reinterpret_cast<__half2*>(&u2.y),
                              *reinterpret_cast<__half2*>(&u3.y));
        float2 a = __half22float2(x01);
        float2 b = __half22float2(x23);
        float2 c = __half22float2(y01);
        float2 d = __half22float2(y23);
        acc.x += a.x + b.x;
        acc.y += a.y + b.y;
        acc.z += c.x + d.x;
        acc.w += c.y + d.y;
    }
    for (; k < end; k++)
        acc_u2(acc, *(const uint2*)(hin + (size_t)g_csr[k] * TT + lo));
    return acc;
}

// Fused agg + mean + relu + next conv (layers 1, 2).
__global__ void agg_conv_kernel(const __half* __restrict__ hin,
                                __half* __restrict__ hout,
                                const float* __restrict__ cw,
                                const float* __restrict__ cb,
                                int layer) {
    int n = blockIdx.x * 8 + (threadIdx.x >> 5);
    int lane = threadIdx.x & 31;
    if (n >= NV) return;
    float4 acc = aggregate(hin, n, lane);
    float inv = g_inv[n];
    float4 v;
    v.x = fmaxf(acc.x * inv, 0.f);
    v.y = fmaxf(acc.y * inv, 0.f);
    v.z = fmaxf(acc.z * inv, 0.f);
    v.w = fmaxf(acc.w * inv, 0.f);
    float wt[KK];
#pragma unroll
    for (int q = 0; q < KK; q++) wt[q] = cw[layer * KK + q];
    v = conv_shfl(v, wt, cb[layer], lane);
    store_row(hout, n, lane, v);
}

// Fused final agg + mean + relu + output matvec with flat-reshape semantics:
// value of node n at time t sits at flat f = n*128+t of x.reshape(128, NV);
// contributes to out[i = f/NV, c] with weight W[c*NV + (f%NV)].
// Fast path: whole node-row inside one output row (all but 127 nodes).
__global__ void agg_out_kernel(const __half* __restrict__ hin,
                               const float* __restrict__ W,
                               float* __restrict__ out) {
    __shared__ float sm[8][TT * 3];   // per-warp accumulator banks
    int w = threadIdx.x >> 5, lane = threadIdx.x & 31;
    for (int i = threadIdx.x; i < 8 * TT * 3; i += 256)
        ((float*)sm)[i] = 0.f;
    __syncthreads();

    int stride = gridDim.x * 8;
    for (int n = blockIdx.x * 8 + w; n < NV; n += stride) {
        float4 acc = aggregate(hin, n, lane);
        float inv = g_inv[n];
        float v[4];
        v[0] = fmaxf(acc.x * inv, 0.f);
        v[1] = fmaxf(acc.y * inv, 0.f);
        v[2] = fmaxf(acc.z * inv, 0.f);
        v[3] = fmaxf(acc.w * inv, 0.f);

        int fbase = n * TT;              // flat index of t=0
        int i0 = fbase / NV;
        int j0 = fbase - i0 * NV;        // column of t=0 (multiple of 4)

        if (j0 + TT <= NV) {
            // Fast path: single output row; coalesced float4 W loads.
            int j = j0 + lane * 4;
            float4 w0 = *(const float4*)(W + j);
            float4 w1 = *(const float4*)(W + NV + j);
            float4 w2 = *(const float4*)(W + 2 * NV + j);
            float s0 = v[0] * w0.x + v[1] * w0.y + v[2] * w0.z + v[3] * w0.w;
            float s1 = v[0] * w1.x + v[1] * w1.y + v[2] * w1.z + v[3] * w1.w;
            float s2 = v[0] * w2.x + v[1] * w2.y + v[2] * w2.z + v[3] * w2.w;
#pragma unroll
            for (int off = 16; off; off >>= 1) {
                s0 += __shfl_down_sync(~0u, s0, off);
                s1 += __shfl_down_sync(~0u, s1, off);
                s2 += __shfl_down_sync(~0u, s2, off);
            }
            if (lane == 0) {
                sm[w][i0 * 3 + 0] += s0;
                sm[w][i0 * 3 + 1] += s1;
                sm[w][i0 * 3 + 2] += s2;
            }
        } else {
            // Slow path: node-row straddles an output-row boundary.
            int B = (i0 + 1) * NV;
            int f = fbase + lane * 4;
            float s0[3] = {0.f, 0.f, 0.f}, s1[3] = {0.f, 0.f, 0.f};
#pragma unroll
            for (int q = 0; q < 4; q++) {
                int fq = f + q;
                bool hi = fq >= B;
                int j = fq - (hi ? B : i0 * NV);
                float w0 = __ldg(W + j);
                float w1 = __ldg(W + NV + j);
                float w2 = __ldg(W + 2 * NV + j);
                if (hi) { s1[0] += v[q] * w0; s1[1] += v[q] * w1; s1[2] += v[q] * w2; }
                else    { s0[0] += v[q] * w0; s0[1] += v[q] * w1; s0[2] += v[q] * w2; }
            }
#pragma unroll
            for (int off = 16; off; off >>= 1) {
                s0[0] += __shfl_down_sync(~0u, s0[0], off);
                s0[1] += __shfl_down_sync(~0u, s0[1], off);
                s0[2] += __shfl_down_sync(~0u, s0[2], off);
                s1[0] += __shfl_down_sync(~0u, s1[0], off);
                s1[1] += __shfl_down_sync(~0u, s1[1], off);
                s1[2] += __shfl_down_sync(~0u, s1[2], off);
            }
            if (lane == 0) {
                sm[w][i0 * 3 + 0] += s0[0];
                sm[w][i0 * 3 + 1] += s0[1];
                sm[w][i0 * 3 + 2] += s0[2];
                sm[w][(i0 + 1) * 3 + 0] += s1[0];
                sm[w][(i0 + 1) * 3 + 1] += s1[1];
                sm[w][(i0 + 1) * 3 + 2] += s1[2];
            }
        }
    }
    __syncthreads();
    for (int i = threadIdx.x; i < TT * 3; i += 256) {
        float s = 0.f;
#pragma unroll
        for (int ww = 0; ww < 8; ww++) s += sm[ww][i];
        atomicAdd(&out[i], s);
    }
}

// ---------------------------------------------------------------------------
extern "C" void kernel_launch(void* const* d_in, const int* in_sizes, int n_in,
                              void* d_out, int out_size) {
    const float* x  = (const float*)d_in[0];
    const int*   ei = (const int*)  d_in[1];
    const float* cw = (const float*)d_in[2];
    const float* cb = (const float*)d_in[3];
    const float* W  = (const float*)d_in[4];
    const float* bo = (const float*)d_in[5];
    float* out = (float*)d_out;

    __half *hA, *hB;
    cudaGetSymbolAddress((void**)&hA, g_hA);
    cudaGetSymbolAddress((void**)&hB, g_hB);

    // CSR build; g_deg is zero (load-time init on call 1, re-zeroed by
    // fill_kernel's tail blocks on every call for graph replays).
    count_conv0_kernel<<<CNT_BLK + CONV_BLK, 256>>>(ei, bo, out, x, cw, cb, hA);
    scan_kernel<<<NCHUNK, 1024>>>();
    fill_kernel<<<CNT_BLK + ZERO_BLK, 256>>>(ei);

    int gagg = (NV + 7) / 8;
    agg_conv_kernel<<<gagg, 256>>>(hA, hB, cw, cb, 1);
    agg_conv_kernel<<<gagg, 256>>>(hB, hA, cw, cb, 2);
    agg_out_kernel<<<1184, 256>>>(hA, W, out);
}